// round 6
// baseline (speedup 1.0000x reference)
#include <cuda_runtime.h>
#include <cuda_bf16.h>
#include <cuda_fp16.h>
#include <cstdint>
#include <cstddef>

#define NNODES 50000
#define NFEAT  128
#define KTOP   32
#define EDGES  800000
#define FULLM  0xFFFFFFFFu

// ---------------- device scratch (no allocation allowed) ----------------
__device__ int   g_cnt[NNODES];
__device__ int   g_rowstart[NNODES];
__device__ int   g_cursor[NNODES];
__device__ int   g_bsum[256];
__device__ int   g_boff[256];
__device__ int   g_col[EDGES];
__device__ __align__(16) __half g_Yh[NNODES * NFEAT];   // Y = Xsp @ W_neigh (fp16)
__device__ __align__(16) float  g_hagg[NNODES * NFEAT]; // normalized neighbor aggregate

// ===========================================================================
// CSR build (by dst): histogram -> scan -> fill
// ===========================================================================
__global__ void count_kernel(const int* __restrict__ dst, int e) {
    int i = blockIdx.x * blockDim.x + threadIdx.x;
    if (i < e) atomicAdd(&g_cnt[dst[i]], 1);
}

__global__ void blocksum_kernel() {
    int i = blockIdx.x * 256 + threadIdx.x;
    int v = (i < NNODES) ? g_cnt[i] : 0;
#pragma unroll
    for (int o = 16; o > 0; o >>= 1) v += __shfl_down_sync(FULLM, v, o);
    __shared__ int ws[8];
    if ((threadIdx.x & 31) == 0) ws[threadIdx.x >> 5] = v;
    __syncthreads();
    if (threadIdx.x == 0) {
        int t = 0;
#pragma unroll
        for (int k = 0; k < 8; k++) t += ws[k];
        g_bsum[blockIdx.x] = t;
    }
}

__global__ void scanpartials_kernel(int nblk) {
    __shared__ int sh[256];
    int t = threadIdx.x;
    int v = (t < nblk) ? g_bsum[t] : 0;
    sh[t] = v;
    __syncthreads();
#pragma unroll
    for (int o = 1; o < 256; o <<= 1) {
        int x = (t >= o) ? sh[t - o] : 0;
        __syncthreads();
        sh[t] += x;
        __syncthreads();
    }
    g_boff[t] = sh[t] - v;
}

__global__ void localscan_kernel() {
    __shared__ int sh[256];
    int t = threadIdx.x;
    int i = blockIdx.x * 256 + t;
    int v = (i < NNODES) ? g_cnt[i] : 0;
    sh[t] = v;
    __syncthreads();
#pragma unroll
    for (int o = 1; o < 256; o <<= 1) {
        int x = (t >= o) ? sh[t - o] : 0;
        __syncthreads();
        sh[t] += x;
        __syncthreads();
    }
    if (i < NNODES) {
        int excl = sh[t] - v + g_boff[blockIdx.x];
        g_rowstart[i] = excl;
        g_cursor[i]   = excl;
    }
}

__global__ void fill_kernel(const int* __restrict__ src, const int* __restrict__ dst, int e) {
    int i = blockIdx.x * blockDim.x + threadIdx.x;
    if (i < e) {
        int pos = atomicAdd(&g_cursor[dst[i]], 1);
        g_col[pos] = src[i];
    }
}

// ===========================================================================
// K4: Y[row] = x_sparse[row] @ W_neigh, dedup (last-k-wins), fp16 output
// ===========================================================================
__global__ __launch_bounds__(256)
void y_kernel(const int* __restrict__ tindices,
              const float* __restrict__ tvalues,
              const float* __restrict__ Wneigh, int n) {
    int wrp  = blockIdx.x * 8 + (threadIdx.x >> 5);
    int lane = threadIdx.x & 31;
    if (wrp >= n) return;
    int   idx = tindices[wrp * KTOP + lane];
    float v   = tvalues[wrp * KTOP + lane];
    unsigned m = __match_any_sync(FULLM, idx);
    if (lane != 31 - __clz(m)) v = 0.0f;

    float4 acc = make_float4(0.f, 0.f, 0.f, 0.f);
#pragma unroll
    for (int k = 0; k < KTOP; k++) {
        int   ik = __shfl_sync(FULLM, idx, k);
        float vk = __shfl_sync(FULLM, v, k);
        if (vk != 0.0f) {
            float4 w = __ldg((const float4*)(Wneigh + ik * NFEAT) + lane);
            acc.x = fmaf(vk, w.x, acc.x);
            acc.y = fmaf(vk, w.y, acc.y);
            acc.z = fmaf(vk, w.z, acc.z);
            acc.w = fmaf(vk, w.w, acc.w);
        }
    }
    __half2 h0 = __floats2half2_rn(acc.x, acc.y);
    __half2 h1 = __floats2half2_rn(acc.z, acc.w);
    uint2 o;
    o.x = *(uint32_t*)&h0;
    o.y = *(uint32_t*)&h1;
    *((uint2*)(g_Yh + (size_t)wrp * NFEAT) + lane) = o;
}

// ===========================================================================
// K5: CSR gather: hagg[d] = (1/max(deg,1)) * sum Y[s], fp16 in / fp32 out
// ===========================================================================
__global__ __launch_bounds__(256)
void gather_kernel(int n) {
    int d    = blockIdx.x * 8 + (threadIdx.x >> 5);
    int lane = threadIdx.x & 31;
    if (d >= n) return;
    int start = g_rowstart[d];
    int cnt   = g_cnt[d];

    float4 acc = make_float4(0.f, 0.f, 0.f, 0.f);
    for (int i = 0; i < cnt; i += 32) {
        int s = (i + lane < cnt) ? g_col[start + i + lane] : 0;
        int m = min(32, cnt - i);
        int j = 0;
        for (; j + 4 <= m; j += 4) {
#pragma unroll
            for (int q = 0; q < 4; q++) {
                int sj = __shfl_sync(FULLM, s, j + q);
                uint2 y = *((const uint2*)(g_Yh + (size_t)sj * NFEAT) + lane);
                float2 f0 = __half22float2(*(__half2*)&y.x);
                float2 f1 = __half22float2(*(__half2*)&y.y);
                acc.x += f0.x; acc.y += f0.y; acc.z += f1.x; acc.w += f1.y;
            }
        }
        for (; j < m; j++) {
            int sj = __shfl_sync(FULLM, s, j);
            uint2 y = *((const uint2*)(g_Yh + (size_t)sj * NFEAT) + lane);
            float2 f0 = __half22float2(*(__half2*)&y.x);
            float2 f1 = __half22float2(*(__half2*)&y.y);
            acc.x += f0.x; acc.y += f0.y; acc.z += f1.x; acc.w += f1.y;
        }
    }
    float w = 1.0f / fmaxf((float)cnt, 1.0f);
    float4 o = make_float4(acc.x * w, acc.y * w, acc.z * w, acc.w * w);
    *((float4*)(g_hagg + (size_t)d * NFEAT) + lane) = o;
}

// ===========================================================================
// K6: out = feat @ W_self + b_self + hagg  via mma.sync bf16 split (3 passes)
// CTA: 128x128 tile. 8 warps in 4(m) x 2(n): warp tile 32 x 64.
// K chunks of 64; smem XOR-swizzled for conflict-free ldmatrix.
// ===========================================================================
#define SOFF_A_HI 0
#define SOFF_A_LO 16384
#define SOFF_B_HI 32768
#define SOFF_B_LO 49152
#define GEMM_SMEM 65536

__device__ __forceinline__ uint32_t pkbf(__nv_bfloat16 a, __nv_bfloat16 b) {
    return (uint32_t)__bfloat16_as_ushort(a) | ((uint32_t)__bfloat16_as_ushort(b) << 16);
}

__device__ __forceinline__ void ldsm4(uint32_t* r, uint32_t addr) {
    asm volatile("ldmatrix.sync.aligned.m8n8.x4.shared.b16 {%0,%1,%2,%3}, [%4];"
                 : "=r"(r[0]), "=r"(r[1]), "=r"(r[2]), "=r"(r[3]) : "r"(addr));
}

__device__ __forceinline__ void mma16816(float* d, const uint32_t* a, const uint32_t* b) {
    asm volatile(
        "mma.sync.aligned.m16n8k16.row.col.f32.bf16.bf16.f32 "
        "{%0,%1,%2,%3}, {%4,%5,%6,%7}, {%8,%9}, {%0,%1,%2,%3};"
        : "+f"(d[0]), "+f"(d[1]), "+f"(d[2]), "+f"(d[3])
        : "r"(a[0]), "r"(a[1]), "r"(a[2]), "r"(a[3]), "r"(b[0]), "r"(b[1]));
}

__global__ __launch_bounds__(256)
void gemm_mma(const float* __restrict__ feat,
              const float* __restrict__ Wself,
              const float* __restrict__ bself,
              float* __restrict__ out, int n) {
    extern __shared__ char smem[];
    const uint32_t sb  = (uint32_t)__cvta_generic_to_shared(smem);
    const int tid  = threadIdx.x;
    const int row0 = blockIdx.x * 128;
    const int wid  = tid >> 5;
    const int lane = tid & 31;
    const int wm   = wid & 3;      // m group: 32 rows
    const int wn   = wid >> 2;     // n group: 64 cols

    float acc[2][8][4];
#pragma unroll
    for (int a = 0; a < 2; a++)
#pragma unroll
        for (int b = 0; b < 8; b++)
#pragma unroll
            for (int c = 0; c < 4; c++) acc[a][b][c] = 0.0f;

#pragma unroll 1
    for (int k0 = 0; k0 < NFEAT; k0 += 64) {
        // ---- stage A (128 rows x 64 k) hi/lo bf16, swizzled [row][k] ----
#pragma unroll
        for (int i = 0; i < 8; i++) {
            int f   = tid + i * 256;     // float4 id 0..2047
            int row = f >> 4;
            int kq  = f & 15;            // float4 within 64-float row chunk
            int gr  = min(row0 + row, n - 1);
            float4 v = __ldg((const float4*)feat + (size_t)gr * 32 + (k0 >> 2) + kq);
            __nv_bfloat16 h0 = __float2bfloat16(v.x), h1 = __float2bfloat16(v.y);
            __nv_bfloat16 h2 = __float2bfloat16(v.z), h3 = __float2bfloat16(v.w);
            __nv_bfloat16 l0 = __float2bfloat16(v.x - __bfloat162float(h0));
            __nv_bfloat16 l1 = __float2bfloat16(v.y - __bfloat162float(h1));
            __nv_bfloat16 l2 = __float2bfloat16(v.z - __bfloat162float(h2));
            __nv_bfloat16 l3 = __float2bfloat16(v.w - __bfloat162float(h3));
            uint2 hv, lv;
            hv.x = pkbf(h0, h1); hv.y = pkbf(h2, h3);
            lv.x = pkbf(l0, l1); lv.y = pkbf(l2, l3);
            uint32_t off = (uint32_t)row * 128
                         + ((((uint32_t)(kq >> 1)) ^ ((uint32_t)row & 7)) << 4)
                         + ((kq & 1) << 3);
            *(uint2*)(smem + SOFF_A_HI + off) = hv;
            *(uint2*)(smem + SOFF_A_LO + off) = lv;
        }
        // ---- stage B: Bt[n][k] = Wself[k0+k][n], swizzled, hi/lo ----
        {
            int nn = tid & 127;
            int kg = (tid >> 7) << 5;    // 0 or 32
            const float* wp = Wself + (size_t)(k0 + kg) * NFEAT + nn;
#pragma unroll
            for (int j0 = 0; j0 < 32; j0 += 8) {
                uint32_t hv[4], lv[4];
#pragma unroll
                for (int q = 0; q < 4; q++) {
                    float x0 = __ldg(wp + (j0 + 2 * q) * NFEAT);
                    float x1 = __ldg(wp + (j0 + 2 * q + 1) * NFEAT);
                    __nv_bfloat16 a0 = __float2bfloat16(x0), a1 = __float2bfloat16(x1);
                    __nv_bfloat16 b0 = __float2bfloat16(x0 - __bfloat162float(a0));
                    __nv_bfloat16 b1 = __float2bfloat16(x1 - __bfloat162float(a1));
                    hv[q] = pkbf(a0, a1);
                    lv[q] = pkbf(b0, b1);
                }
                uint32_t off = (uint32_t)nn * 128
                             + ((((uint32_t)((kg + j0) >> 3)) ^ ((uint32_t)nn & 7)) << 4);
                *(uint4*)(smem + SOFF_B_HI + off) = *(uint4*)hv;
                *(uint4*)(smem + SOFF_B_LO + off) = *(uint4*)lv;
            }
        }
        __syncthreads();

        // ---- compute: 4 k16 steps ----
#pragma unroll
        for (int ks = 0; ks < 4; ks++) {
            // A fragments (2 m-tiles of 16 rows)
            uint32_t ah[2][4], al[2][4];
            {
                int arow = wm * 32 + (lane & 7) + ((lane >> 3) & 1) * 8;
                int ak8  = ks * 2 + (lane >> 4);
                uint32_t aoff = (uint32_t)arow * 128
                              + (((uint32_t)ak8 ^ ((uint32_t)arow & 7)) << 4);
                ldsm4(ah[0], sb + SOFF_A_HI + aoff);
                ldsm4(ah[1], sb + SOFF_A_HI + aoff + 2048);
                ldsm4(al[0], sb + SOFF_A_LO + aoff);
                ldsm4(al[1], sb + SOFF_A_LO + aoff + 2048);
            }
            // B: 4 n-pairs of 16 cols
            int nrow0 = wn * 64 + (lane & 7) + ((lane >> 4) & 1) * 8;
            int bk8   = ks * 2 + ((lane >> 3) & 1);
#pragma unroll
            for (int np = 0; np < 4; np++) {
                int nrow = nrow0 + np * 16;
                uint32_t boff = (uint32_t)nrow * 128
                              + (((uint32_t)bk8 ^ ((uint32_t)nrow & 7)) << 4);
                uint32_t bh[4], bl[4];
                ldsm4(bh, sb + SOFF_B_HI + boff);
                ldsm4(bl, sb + SOFF_B_LO + boff);
#pragma unroll
                for (int mt = 0; mt < 2; mt++) {
                    mma16816(acc[mt][np * 2 + 0], ah[mt], bh + 0);
                    mma16816(acc[mt][np * 2 + 0], ah[mt], bl + 0);
                    mma16816(acc[mt][np * 2 + 0], al[mt], bh + 0);
                    mma16816(acc[mt][np * 2 + 1], ah[mt], bh + 2);
                    mma16816(acc[mt][np * 2 + 1], ah[mt], bl + 2);
                    mma16816(acc[mt][np * 2 + 1], al[mt], bh + 2);
                }
            }
        }
        __syncthreads();
    }

    // ---- epilogue: + bias + hagg ----
    const int qrow = lane >> 2;
    const int qcol = (lane & 3) * 2;
#pragma unroll
    for (int mt = 0; mt < 2; mt++) {
        int r1 = row0 + wm * 32 + mt * 16 + qrow;
        int r2 = r1 + 8;
#pragma unroll
        for (int nt = 0; nt < 8; nt++) {
            int col = wn * 64 + nt * 8 + qcol;
            float2 b = *(const float2*)(bself + col);
            if (r1 < n) {
                float2 h = *(const float2*)(g_hagg + (size_t)r1 * NFEAT + col);
                float2 o;
                o.x = acc[mt][nt][0] + b.x + h.x;
                o.y = acc[mt][nt][1] + b.y + h.y;
                *(float2*)(out + (size_t)r1 * NFEAT + col) = o;
            }
            if (r2 < n) {
                float2 h = *(const float2*)(g_hagg + (size_t)r2 * NFEAT + col);
                float2 o;
                o.x = acc[mt][nt][2] + b.x + h.x;
                o.y = acc[mt][nt][3] + b.y + h.y;
                *(float2*)(out + (size_t)r2 * NFEAT + col) = o;
            }
        }
    }
}

// ===========================================================================
// Launch. Inputs: 0 feat | 1 topk_values | 2 topk_indices | 3 src | 4 dst |
//                 5 W_self | 6 b_self | 7 W_neigh
// ===========================================================================
extern "C" void kernel_launch(void* const* d_in, const int* in_sizes, int n_in,
                              void* d_out, int out_size) {
    const float* feat     = (const float*)d_in[0];
    const float* tvalues  = (const float*)d_in[1];
    const int*   tindices = (const int*)d_in[2];
    const int*   src      = (const int*)d_in[3];
    const int*   dst      = (const int*)d_in[4];
    const float* Wself    = (const float*)d_in[5];
    const float* bself    = (const float*)d_in[6];
    const float* Wneigh   = (const float*)d_in[7];
    float*       out      = (float*)d_out;

    const int n = in_sizes[0] / NFEAT;   // 50000
    const int e = in_sizes[3];           // 800000

    cudaFuncSetAttribute(gemm_mma, cudaFuncAttributeMaxDynamicSharedMemorySize,
                         GEMM_SMEM);

    void* cntp;
    cudaGetSymbolAddress(&cntp, g_cnt);
    cudaMemsetAsync(cntp, 0, (size_t)n * sizeof(int));

    const int nblk = (n + 255) / 256;

    count_kernel<<<(e + 255) / 256, 256>>>(dst, e);
    blocksum_kernel<<<nblk, 256>>>();
    scanpartials_kernel<<<1, 256>>>(nblk);
    localscan_kernel<<<nblk, 256>>>();
    fill_kernel<<<(e + 255) / 256, 256>>>(src, dst, e);

    y_kernel<<<(n + 7) / 8, 256>>>(tindices, tvalues, Wneigh, n);
    gather_kernel<<<(n + 7) / 8, 256>>>(n);
    gemm_mma<<<(n + 127) / 128, 256, GEMM_SMEM>>>(feat, Wself, bself, out, n);
}